// round 2
// baseline (speedup 1.0000x reference)
#include <cuda_runtime.h>
#include <cuda_bf16.h>
#include <math.h>

#define BB   512   // batch
#define TT   128   // time steps
#define FF   256   // features
#define HH   512   // hidden
#define KK   3     // fuzzy rules

typedef unsigned long long ull;

// ------------------------------------------------------------------
// Device scratch
// ------------------------------------------------------------------
__device__ float g_xw[(size_t)TT * BB * HH];   // [T][B][H]
__device__ float g_hT[2][(size_t)HH * BB];     // transposed hidden state [H][B], ping-pong
__device__ float g_Wxs[FF * HH];               // diag(sigmoid(theta)) @ Wx
__device__ float g_invden[HH * KK];            // 1/(2*sigma^2 + 1e-8)

// ------------------------------------------------------------------
// Packed f32x2 helpers
// ------------------------------------------------------------------
__device__ __forceinline__ ull pack2(float x, float y) {
    ull r; asm("mov.b64 %0, {%1, %2};" : "=l"(r) : "f"(x), "f"(y)); return r;
}
__device__ __forceinline__ float2 unpack2(ull v) {
    float2 r; asm("mov.b64 {%0, %1}, %2;" : "=f"(r.x), "=f"(r.y) : "l"(v)); return r;
}
__device__ __forceinline__ ull fma2(ull a, ull b, ull c) {
    ull d; asm("fma.rn.f32x2 %0, %1, %2, %3;" : "=l"(d) : "l"(a), "l"(b), "l"(c)); return d;
}

// ------------------------------------------------------------------
// Prep
// ------------------------------------------------------------------
__global__ void prep_kernel(const float* __restrict__ theta,
                            const float* __restrict__ Wx,
                            const float* __restrict__ sigma,
                            float* __restrict__ out)
{
    int idx = blockIdx.x * blockDim.x + threadIdx.x;
    if (idx < FF * HH) {
        int f = idx >> 9;
        float w = 1.0f / (1.0f + expf(-theta[f]));
        g_Wxs[idx] = w * Wx[idx];
    }
    if (idx < FF) out[BB + idx] = 1.0f / (1.0f + expf(-theta[idx]));
    if (idx < HH * KK) {
        float s = sigma[idx];
        g_invden[idx] = 1.0f / (2.0f * s * s + 1e-8f);
    }
}

// ------------------------------------------------------------------
// GEMM1: g_xw[t][b][h] = sum_f x[b][t][f] * Wxs[f][h]   (unchanged, known good)
// ------------------------------------------------------------------
__global__ void __launch_bounds__(256) gemm1_kernel(const float* __restrict__ x)
{
    __shared__ float sA[16][130];
    __shared__ float sB[16][128];

    const int tid = threadIdx.x;
    const int m0  = blockIdx.x * 128;
    const int n0  = blockIdx.y * 128;

    const int ar = tid >> 1;
    const int ak = (tid & 1) * 8;
    const int bk = tid >> 4;
    const int bc = (tid & 15) * 8;

    const float* Ag = x     + (size_t)(m0 + ar) * FF + ak;
    const float* Bg = g_Wxs + (size_t)bk * HH + n0 + bc;

    float4 ra0 = *(const float4*)(Ag);
    float4 ra1 = *(const float4*)(Ag + 4);
    float4 rb0 = *(const float4*)(Bg);
    float4 rb1 = *(const float4*)(Bg + 4);

    ull acc[4][8];
    #pragma unroll
    for (int i = 0; i < 4; ++i)
        #pragma unroll
        for (int j = 0; j < 8; ++j) acc[i][j] = 0ull;

    const int ty = tid >> 4;
    const int tx = tid & 15;

    #pragma unroll 1
    for (int kt = 0; kt < FF / 16; ++kt) {
        sA[ak + 0][ar] = ra0.x; sA[ak + 1][ar] = ra0.y;
        sA[ak + 2][ar] = ra0.z; sA[ak + 3][ar] = ra0.w;
        sA[ak + 4][ar] = ra1.x; sA[ak + 5][ar] = ra1.y;
        sA[ak + 6][ar] = ra1.z; sA[ak + 7][ar] = ra1.w;
        *(float4*)&sB[bk][bc]     = rb0;
        *(float4*)&sB[bk][bc + 4] = rb1;
        __syncthreads();

        if (kt < FF / 16 - 1) {
            const float* Ag2 = Ag + (kt + 1) * 16;
            const float* Bg2 = Bg + (size_t)(kt + 1) * 16 * HH;
            ra0 = *(const float4*)(Ag2);
            ra1 = *(const float4*)(Ag2 + 4);
            rb0 = *(const float4*)(Bg2);
            rb1 = *(const float4*)(Bg2 + 4);
        }

        #pragma unroll
        for (int kk = 0; kk < 16; ++kk) {
            ull a2[4];
            #pragma unroll
            for (int i = 0; i < 4; ++i)
                a2[i] = *(const ull*)&sA[kk][ty * 8 + 2 * i];
            float bf[8];
            *(float4*)&bf[0] = *(const float4*)&sB[kk][tx * 8];
            *(float4*)&bf[4] = *(const float4*)&sB[kk][tx * 8 + 4];
            #pragma unroll
            for (int j = 0; j < 8; ++j) {
                ull bbv = pack2(bf[j], bf[j]);
                #pragma unroll
                for (int i = 0; i < 4; ++i)
                    acc[i][j] = fma2(a2[i], bbv, acc[i][j]);
            }
        }
        __syncthreads();
    }

    #pragma unroll
    for (int i = 0; i < 4; ++i) {
        float2 v[8];
        #pragma unroll
        for (int j = 0; j < 8; ++j) v[j] = unpack2(acc[i][j]);
        #pragma unroll
        for (int p = 0; p < 2; ++p) {
            int m = m0 + ty * 8 + 2 * i + p;
            int t = m & (TT - 1);
            int b = m >> 7;
            float* orow = g_xw + ((size_t)t * BB + b) * HH + n0 + tx * 8;
            float4 o0, o1;
            if (p == 0) {
                o0 = make_float4(v[0].x, v[1].x, v[2].x, v[3].x);
                o1 = make_float4(v[4].x, v[5].x, v[6].x, v[7].x);
            } else {
                o0 = make_float4(v[0].y, v[1].y, v[2].y, v[3].y);
                o1 = make_float4(v[4].y, v[5].y, v[6].y, v[7].y);
            }
            *(float4*)(orow)     = o0;
            *(float4*)(orow + 4) = o1;
        }
    }
}

// ------------------------------------------------------------------
// Persistent recurrence kernel.
// Grid = 128 CTAs, clusters of 8. Cluster = one 32-row batch tile.
// ctarank = n-slice (64 hidden cols). Wh slice lives in smem for all 128
// steps; h tile staged in smem per step; exchange via transposed global
// ping-pong buffers + barrier.cluster.
// ------------------------------------------------------------------
__global__ void __launch_bounds__(256, 1) __cluster_dims__(8, 1, 1)
rnn_persistent(const float* __restrict__ Wh,
               const float* __restrict__ bias,
               const float* __restrict__ cC,
               const float* __restrict__ qQ)
{
    extern __shared__ float smem[];
    float* sB = smem;                 // [512][64]  Wh slice
    float* sA = smem + HH * 64;       // [512][32]  h tile (k-major, m minor)

    const int tid  = threadIdx.x;
    const int m0   = (blockIdx.x >> 3) * 32;   // batch tile
    const int n0   = (blockIdx.x & 7) * 64;    // hidden slice

    // warp microtile mapping
    const int warp = tid >> 5;
    const int lane = tid & 31;
    const int wm   = warp & 1;          // 2 warps over m (16 rows each)
    const int wn   = warp >> 1;         // 4 warps over n (16 cols each)
    const int mp   = lane & 7;          // 8 row-pairs
    const int nq   = lane >> 3;         // 4 col-quads
    const int aoff = wm * 16 + mp * 2;  // local row (pair base)
    const int boff = wn * 16 + nq * 4;  // local col (quad base)
    const int colbase = n0 + boff;      // global col of quad

    // ---- load Wh slice into smem (once) ----
    {
        const int j4 = tid & 15;        // 16 float4 = 64 cols
        const int kr = tid >> 4;        // 16 k rows per pass
        #pragma unroll
        for (int i = 0; i < 32; ++i) {
            int k = kr + i * 16;
            float4 v = *(const float4*)&Wh[(size_t)k * HH + n0 + j4 * 4];
            *(float4*)&sA[0] ; // (no-op guard removed below)
            *(float4*)&sB[k * 64 + j4 * 4] = v;
        }
    }

    // ---- per-thread gate constants (4 columns) ----
    float rc[4][3], ri[4][3], rq[4][3], rb[4];
    #pragma unroll
    for (int j = 0; j < 4; ++j) {
        int col = colbase + j;
        #pragma unroll
        for (int s = 0; s < 3; ++s) {
            rc[j][s] = cC[col * 3 + s];
            ri[j][s] = g_invden[col * 3 + s];
            rq[j][s] = qQ[col * 3 + s];
        }
        rb[j] = bias[col];
    }

    // ---- zero sA (h0 = 0) ----
    for (int i = tid; i < HH * 32 / 4; i += 256)
        *(float4*)&sA[i * 4] = make_float4(0.f, 0.f, 0.f, 0.f);
    __syncthreads();

    const float* ap = sA + aoff;
    const float* bp = sB + boff;

    for (int t = 0; t < TT; ++t) {
        // ---- GEMM: acc = h_t[m-tile] @ Wh[:, n-slice] ----
        ull acc0 = 0, acc1 = 0, acc2 = 0, acc3 = 0;
        #pragma unroll 8
        for (int k = 0; k < HH; ++k) {
            ull    a2 = *(const ull*)(ap + k * 32);
            float4 bv = *(const float4*)(bp + k * 64);
            acc0 = fma2(a2, pack2(bv.x, bv.x), acc0);
            acc1 = fma2(a2, pack2(bv.y, bv.y), acc1);
            acc2 = fma2(a2, pack2(bv.z, bv.z), acc2);
            acc3 = fma2(a2, pack2(bv.w, bv.w), acc3);
        }

        // ---- fused gate epilogue ----
        const int r0 = m0 + aoff;
        const float* xwt = g_xw + (size_t)t * (BB * HH);
        float4 xv0 = *(const float4*)&xwt[(size_t)r0 * HH + colbase];
        float4 xv1 = *(const float4*)&xwt[(size_t)(r0 + 1) * HH + colbase];
        float xa0[4] = {xv0.x, xv0.y, xv0.z, xv0.w};
        float xa1[4] = {xv1.x, xv1.y, xv1.z, xv1.w};
        ull accs[4] = {acc0, acc1, acc2, acc3};
        float* hdst = g_hT[(t + 1) & 1];

        #pragma unroll
        for (int j = 0; j < 4; ++j) {
            const int col = colbase + j;
            float2 hin2 = unpack2(*(const ull*)&sA[col * 32 + aoff]);
            float2 zz   = unpack2(accs[j]);
            float hn[2];
            #pragma unroll
            for (int p = 0; p < 2; ++p) {
                float xv  = p ? xa1[j] : xa0[j];
                float hin = p ? hin2.y : hin2.x;
                float z   = (p ? zz.y : zz.x) + xv + rb[j];
                float d0 = z - rc[j][0], d1 = z - rc[j][1], d2 = z - rc[j][2];
                float mu0 = __expf(-d0 * d0 * ri[j][0]);
                float mu1 = __expf(-d1 * d1 * ri[j][1]);
                float mu2 = __expf(-d2 * d2 * ri[j][2]);
                float num = mu0 * rq[j][0] + mu1 * rq[j][1] + mu2 * rq[j][2];
                float den = mu0 + mu1 + mu2 + 1e-8f;
                float g   = 1.0f / (1.0f + __expf(-num / den));
                // tanh(xv) = (1 - e^{-2x}) / (1 + e^{-2x})
                float ex  = __expf(-2.0f * xv);
                float ni  = (1.0f - ex) / (1.0f + ex);
                hn[p] = (1.0f - g) * hin + g * ni;
            }
            *(float2*)&hdst[(size_t)col * BB + r0] = make_float2(hn[0], hn[1]);
        }

        __syncthreads();          // all sA reads in this CTA complete
        __threadfence();          // publish hdst to L2 for cluster peers
        asm volatile("barrier.cluster.arrive.aligned;" ::: "memory");
        asm volatile("barrier.cluster.wait.aligned;"   ::: "memory");

        // ---- stage h_{t+1} into sA ----
        if (t < TT - 1) {
            const float* hsrc = g_hT[(t + 1) & 1];
            const int m4 = tid & 7;
            const int kb = tid >> 3;
            #pragma unroll
            for (int i = 0; i < 16; ++i) {
                int k = kb + i * 32;
                float4 v = *(const float4*)&hsrc[(size_t)k * BB + m0 + m4 * 4];
                *(float4*)&sA[k * 32 + m4 * 4] = v;
            }
            __syncthreads();
        }
    }
}

// ------------------------------------------------------------------
// Final: logits[b] = h_T[:,b] . Wc + bc ;  h_T lives in g_hT[0]
// ------------------------------------------------------------------
__global__ void final_kernel(const float* __restrict__ Wc,
                             const float* __restrict__ bc,
                             float* __restrict__ out)
{
    const int b = threadIdx.x;   // 512 threads, one per batch row
    const float* hT = g_hT[0];
    float s = 0.0f;
    #pragma unroll 8
    for (int h = 0; h < HH; ++h)
        s += hT[(size_t)h * BB + b] * Wc[h];
    out[b] = s + bc[0];
}

// ------------------------------------------------------------------
// Launch
// ------------------------------------------------------------------
extern "C" void kernel_launch(void* const* d_in, const int* in_sizes, int n_in,
                              void* d_out, int out_size)
{
    const float* x     = (const float*)d_in[0];
    const float* theta = (const float*)d_in[1];
    const float* Wx    = (const float*)d_in[2];
    const float* Wh    = (const float*)d_in[3];
    const float* bias  = (const float*)d_in[4];
    const float* c     = (const float*)d_in[5];
    const float* sigma = (const float*)d_in[6];
    const float* q     = (const float*)d_in[7];
    const float* Wc    = (const float*)d_in[8];
    const float* bc    = (const float*)d_in[9];
    float* out = (float*)d_out;

    const int smem_bytes = (HH * 64 + HH * 32) * sizeof(float);  // 192 KB
    cudaFuncSetAttribute(rnn_persistent,
                         cudaFuncAttributeMaxDynamicSharedMemorySize, smem_bytes);

    prep_kernel<<<(FF * HH + 255) / 256, 256>>>(theta, Wx, sigma, out);
    gemm1_kernel<<<dim3((BB * TT) / 128, HH / 128), 256>>>(x);
    rnn_persistent<<<128, 256, smem_bytes>>>(Wh, bias, c, q);
    final_kernel<<<1, BB>>>(Wc, bc, out);
}